// round 15
// baseline (speedup 1.0000x reference)
#include <cuda_runtime.h>
#include <cuda_fp16.h>
#include <cstdint>

#define W_BIT 4
#define OUT_F 11008
#define IN_F 4096
#define KRANK 16
#define TOKENS 2048
#define NBYTES (OUT_F * IN_F / 8)

// fp16 staging buffers (static device globals: allocation-free rule)
__device__ __align__(16) __half g_w[(size_t)OUT_F * (size_t)IN_F];
__device__ __align__(16) __half g_x[(size_t)TOKENS * (size_t)IN_F];

// ---------------------------------------------------------------------------
// PTX helpers (baseline compute_103-safe: cp.async / ldmatrix / mma.sync only)
// ---------------------------------------------------------------------------
__device__ __forceinline__ uint32_t smem_u32(const void* p) {
  uint32_t a;
  asm("{ .reg .u64 t; cvta.to.shared.u64 t, %1; cvt.u32.u64 %0, t; }"
      : "=r"(a) : "l"(p));
  return a;
}

#define CP_ASYNC16(dst, src) \
  asm volatile("cp.async.cg.shared.global [%0], [%1], 16;" ::"r"(dst), "l"(src) : "memory")
#define CP_COMMIT() asm volatile("cp.async.commit_group;" ::: "memory")
#define CP_WAIT(n)  asm volatile("cp.async.wait_group %0;" ::"n"(n) : "memory")

#define LDSM_X4(r, addr)                                                  \
  asm volatile(                                                           \
      "ldmatrix.sync.aligned.m8n8.x4.shared.b16 {%0,%1,%2,%3}, [%4];"     \
      : "=r"((r)[0]), "=r"((r)[1]), "=r"((r)[2]), "=r"((r)[3])            \
      : "r"(addr))

#define LDSM_X4_T(r, addr)                                                \
  asm volatile(                                                           \
      "ldmatrix.sync.aligned.m8n8.x4.trans.shared.b16 {%0,%1,%2,%3}, [%4];" \
      : "=r"((r)[0]), "=r"((r)[1]), "=r"((r)[2]), "=r"((r)[3])            \
      : "r"(addr))

#define MMA16816(d, a, b)                                                 \
  asm volatile(                                                           \
      "mma.sync.aligned.m16n8k16.row.col.f32.f16.f16.f32 "                \
      "{%0,%1,%2,%3}, {%4,%5,%6,%7}, {%8,%9}, {%0,%1,%2,%3};"             \
      : "+f"((d)[0]), "+f"((d)[1]), "+f"((d)[2]), "+f"((d)[3])            \
      : "r"((a)[0]), "r"((a)[1]), "r"((a)[2]), "r"((a)[3]),               \
        "r"((b)[0]), "r"((b)[1]))

__device__ __forceinline__ float xor_sign(float p, unsigned s) {
  return __uint_as_float(__float_as_uint(p) ^ s);
}

// ---------------------------------------------------------------------------
// Kernel 0: x -> fp16
// ---------------------------------------------------------------------------
__global__ __launch_bounds__(256) void convert_x_kernel(const float* __restrict__ x) {
  size_t i = ((size_t)blockIdx.x * 256 + threadIdx.x) * 4;
  float4 v = *(const float4*)(x + i);
  __half2 h0 = __floats2half2_rn(v.x, v.y);
  __half2 h1 = __floats2half2_rn(v.z, v.w);
  uint2 p;
  p.x = *(const unsigned*)&h0;
  p.y = *(const unsigned*)&h1;
  *(uint2*)(g_x + i) = p;
}

// ---------------------------------------------------------------------------
// Kernel 1: HMMA reconstruct (R10 version — validated, unchanged).
// ---------------------------------------------------------------------------
#define US_OFF 0
#define US_BSTR (128 * 48)
#define VT_OFF 24576
#define VT_BSTR (16 * 272)
#define QS_OFF (24576 + 17408)
#define RS_TOTAL (QS_OFF + 4 * 128 * 16)  // 50176 B

__global__ __launch_bounds__(256, 1) void reconstruct_hmma_kernel(
    const int* __restrict__ qweight, const float* __restrict__ u,
    const float* __restrict__ vt) {
  extern __shared__ char rs[];
  const uint32_t sb = smem_u32(rs);
  const int tid = threadIdx.x;
  const int lane = tid & 31;
  const int wid = tid >> 5;
  const int wm = wid & 1;
  const int wn = wid >> 1;
  const int i_base = blockIdx.x * 128;
  const int o_base = blockIdx.y * 128;

#pragma unroll
  for (int j = 0; j < 8; j++) {
    const int s = tid + j * 256;
    const int b = s >> 9;
    const int rem = s & 511;

    {  // u
      const int o = rem >> 2, k4 = rem & 3;
      const float4 uf = *(const float4*)(
          u + ((size_t)b * OUT_F + o_base + o) * KRANK + k4 * 4);
      __half2 h0 = __floats2half2_rn(uf.x, uf.y);
      __half2 h1 = __floats2half2_rn(uf.z, uf.w);
      uint2 pk = make_uint2(*(const unsigned*)&h0, *(const unsigned*)&h1);
      *(uint2*)(rs + US_OFF + b * US_BSTR + o * 48 + k4 * 8) = pk;
    }
    {  // vt
      const int k = rem >> 5, c4 = (rem & 31) * 4;
      const float4 vf = *(const float4*)(
          vt + ((size_t)b * KRANK + k) * IN_F + i_base + c4);
      __half2 h0 = __floats2half2_rn(vf.x, vf.y);
      __half2 h1 = __floats2half2_rn(vf.z, vf.w);
      uint2 pk = make_uint2(*(const unsigned*)&h0, *(const unsigned*)&h1);
      *(uint2*)(rs + VT_OFF + b * VT_BSTR + k * 272 + c4 * 2) = pk;
    }
    {  // qweight (with i-tile offset)
      const int o = rem >> 2, q4 = rem & 3;
      const int4 qi = *(const int4*)(
          qweight + (size_t)b * NBYTES + (size_t)(o_base + o) * (IN_F / 8) +
          (i_base >> 3) + q4 * 4);
      const unsigned pk = (unsigned)qi.x | ((unsigned)qi.y << 8) |
                          ((unsigned)qi.z << 16) | ((unsigned)qi.w << 24);
      *(unsigned*)(rs + QS_OFF + b * 2048 + o * 16 + q4 * 4) = pk;
    }
  }
  __syncthreads();

  float acc[4][4][4];
#pragma unroll
  for (int mt = 0; mt < 4; mt++)
#pragma unroll
    for (int nt = 0; nt < 4; nt++)
#pragma unroll
      for (int q = 0; q < 4; q++) acc[mt][nt][q] = 0.0f;

  const int j0 = (lane & 3) * 2;
  const char* qsm = rs + QS_OFF;

#pragma unroll
  for (int b = 0; b < W_BIT; b++) {
    uint32_t af[4][4];
#pragma unroll
    for (int mt = 0; mt < 4; mt++) {
      const uint32_t addr = sb + US_OFF + b * US_BSTR +
                            (wm * 64 + mt * 16 + (lane & 15)) * 48 +
                            (lane >> 4) * 16;
      LDSM_X4(af[mt], addr);
    }
    uint32_t bf[4][2];
#pragma unroll
    for (int p = 0; p < 2; p++) {
      const int k_r = ((lane >> 3) & 1) * 8 + (lane & 7);
      const int n_off = wn * 32 + p * 16 + (lane >> 4) * 8;
      const uint32_t addr = sb + VT_OFF + b * VT_BSTR + k_r * 272 + n_off * 2;
      uint32_t r[4];
      LDSM_X4_T(r, addr);
      bf[p * 2][0] = r[0]; bf[p * 2][1] = r[1];
      bf[p * 2 + 1][0] = r[2]; bf[p * 2 + 1][1] = r[3];
    }

#pragma unroll
    for (int mt = 0; mt < 4; mt++) {
      float p4[4][4];
#pragma unroll
      for (int nt = 0; nt < 4; nt++) {
        p4[nt][0] = 0.0f; p4[nt][1] = 0.0f;
        p4[nt][2] = 0.0f; p4[nt][3] = 0.0f;
        MMA16816(p4[nt], af[mt], bf[nt]);
      }
      const int o_lo = wm * 64 + mt * 16 + (lane >> 2);
      const int o_hi = o_lo + 8;
      const unsigned nb_lo =
          ~*(const unsigned*)(qsm + b * 2048 + o_lo * 16 + wn * 4);
      const unsigned nb_hi =
          ~*(const unsigned*)(qsm + b * 2048 + o_hi * 16 + wn * 4);
#pragma unroll
      for (int nt = 0; nt < 4; nt++) {
        const int sh = nt * 8 + j0;
        acc[mt][nt][0] += xor_sign(p4[nt][0], ((nb_lo >> sh) << 31));
        acc[mt][nt][1] += xor_sign(p4[nt][1], ((nb_lo >> (sh + 1)) << 31));
        acc[mt][nt][2] += xor_sign(p4[nt][2], ((nb_hi >> sh) << 31));
        acc[mt][nt][3] += xor_sign(p4[nt][3], ((nb_hi >> (sh + 1)) << 31));
      }
    }
  }

#pragma unroll
  for (int mt = 0; mt < 4; mt++) {
    const int o_lo = o_base + wm * 64 + mt * 16 + (lane >> 2);
#pragma unroll
    for (int nt = 0; nt < 4; nt++) {
      const int i0 = i_base + wn * 32 + nt * 8 + j0;
      __half2 hlo = __floats2half2_rn(acc[mt][nt][0], acc[mt][nt][1]);
      __half2 hhi = __floats2half2_rn(acc[mt][nt][2], acc[mt][nt][3]);
      *(unsigned*)(g_w + (size_t)o_lo * IN_F + i0) = *(const unsigned*)&hlo;
      *(unsigned*)(g_w + (size_t)(o_lo + 8) * IN_F + i0) = *(const unsigned*)&hhi;
    }
  }
}

// ---------------------------------------------------------------------------
// Kernel 2: HMMA fp16 GEMM, f32 accum. CTA 128x256, BK=128, GS=2,
// 8 warps (2x4), warp tile 64x64: LDSM traffic/iter drops 384->256 KB
// (fragment reuse ∝ warp tile). A+B register ping-pong; 1 barrier/iter.
// ---------------------------------------------------------------------------
#define BM 128
#define BN 256
#define BKK 128
#define GS 2
#define ROWB 272                          // 256B data + 16B pad per row
#define A_ST (BM * ROWB)                  // 34816 B
#define B_ST (BN * ROWB)                  // 69632 B
#define SMEM_TOTAL (GS * (A_ST + B_ST))   // 208896 B
#define NIT (IN_F / BKK)                  // 32
#define NTHR 256

__global__ __launch_bounds__(NTHR, 1) void gemm_hmma_kernel(float* __restrict__ Y) {
  extern __shared__ char smem[];
  const uint32_t sb = smem_u32(smem);
  const int tid = threadIdx.x;
  const int wid = tid >> 5;
  const int lane = tid & 31;
  const int m0 = blockIdx.y * BM;
  const int n0 = blockIdx.x * BN;
  const int wm = wid & 1;   // 2 warp rows (M), 64 each
  const int wn = wid >> 1;  // 4 warp cols (N), 64 each

  const __half* Ag = g_x + (size_t)m0 * IN_F;
  const __half* Bg = g_w + (size_t)n0 * IN_F;

  // fill: A = 2048 slots of 16B (8/thread), B = 4096 slots (16/thread)
  auto fill = [&](int s, int c) {
    const uint32_t ab = sb + s * A_ST;
    const uint32_t bb = sb + GS * A_ST + s * B_ST;
    const int k0 = c * BKK;
#pragma unroll
    for (int j = 0; j < 8; j++) {
      const int slot = tid + j * NTHR;
      const int row = slot >> 4, ch = slot & 15;
      CP_ASYNC16(ab + row * ROWB + ch * 16,
                 Ag + (size_t)row * IN_F + k0 + ch * 8);
    }
#pragma unroll
    for (int j = 0; j < 16; j++) {
      const int slot = tid + j * NTHR;
      const int row = slot >> 4, ch = slot & 15;
      CP_ASYNC16(bb + row * ROWB + ch * 16,
                 Bg + (size_t)row * IN_F + k0 + ch * 8);
    }
    CP_COMMIT();
  };

  float acc[4][8][4];
#pragma unroll
  for (int mt = 0; mt < 4; mt++)
#pragma unroll
    for (int nt = 0; nt < 8; nt++)
#pragma unroll
      for (int q = 0; q < 4; q++) acc[mt][nt][q] = 0.0f;

  fill(0, 0);  // prologue

  const int a_row_l = lane & 15;
  const int a_ch_l = (lane >> 4) * 16;
  const int b_g = lane >> 3;
  const int b_row_l = ((b_g >> 1) * 8) + (lane & 7);
  const int b_ch_l = (b_g & 1) * 16;

  const uint32_t a_lane_off = (wm * 64 + a_row_l) * ROWB + a_ch_l;
  const uint32_t b_lane_off = (wn * 64 + b_row_l) * ROWB + b_ch_l;

  for (int it = 0; it < NIT; it++) {
    CP_WAIT(0);
    __syncthreads();  // single barrier: publishes stage it%GS AND orders
                      // all consumption of the other stage before its refill

    const int c = it + 1;
    if (c < NIT) fill(c % GS, c);

    const int s = it % GS;
    const uint32_t ab = sb + s * A_ST + a_lane_off;
    const uint32_t bb = sb + GS * A_ST + s * B_ST + b_lane_off;

    uint32_t a[2][4][4];   // [buf][mt][frag]
    uint32_t b[2][8][2];   // [buf][nt][frag]

    auto load_a = [&](int buf, int kt) {
#pragma unroll
      for (int mt = 0; mt < 4; mt++)
        LDSM_X4(a[buf][mt], ab + mt * 16 * ROWB + kt * 32);
    };
    auto load_b = [&](int buf, int kt) {
#pragma unroll
      for (int np = 0; np < 4; np++) {
        uint32_t r[4];
        LDSM_X4(r, bb + np * 16 * ROWB + kt * 32);
        b[buf][np * 2][0] = r[0]; b[buf][np * 2][1] = r[1];
        b[buf][np * 2 + 1][0] = r[2]; b[buf][np * 2 + 1][1] = r[3];
      }
    };

    load_b(0, 0);
    load_a(0, 0);

#pragma unroll
    for (int kt = 0; kt < BKK / 16; kt++) {
      const int cur = kt & 1;
      if (kt < BKK / 16 - 1) {
        load_b(cur ^ 1, kt + 1);   // next-kt LDSMs before this kt's MMAs
        load_a(cur ^ 1, kt + 1);
      }
#pragma unroll
      for (int mt = 0; mt < 4; mt++)
#pragma unroll
        for (int nt = 0; nt < 8; nt++)
          MMA16816(acc[mt][nt], a[cur][mt], b[cur][nt]);
    }
  }

#pragma unroll
  for (int mt = 0; mt < 4; mt++) {
#pragma unroll
    for (int nt = 0; nt < 8; nt++) {
      const int r = m0 + wm * 64 + mt * 16 + (lane >> 2);
      const int cc = n0 + wn * 64 + nt * 8 + (lane & 3) * 2;
      float2 v0 = make_float2(acc[mt][nt][0], acc[mt][nt][1]);
      float2 v1 = make_float2(acc[mt][nt][2], acc[mt][nt][3]);
      *(float2*)(Y + (size_t)r * OUT_F + cc) = v0;
      *(float2*)(Y + (size_t)(r + 8) * OUT_F + cc) = v1;
    }
  }
}

// ---------------------------------------------------------------------------
// Launch: inputs in metadata order: x (f32), qweight (i32), u (f32), vt (f32)
// ---------------------------------------------------------------------------
extern "C" void kernel_launch(void* const* d_in, const int* in_sizes, int n_in,
                              void* d_out, int out_size) {
  const float* x = (const float*)d_in[0];
  const int* qweight = (const int*)d_in[1];
  const float* u = (const float*)d_in[2];
  const float* vt = (const float*)d_in[3];
  float* y = (float*)d_out;
  (void)in_sizes; (void)n_in; (void)out_size;

  cudaFuncSetAttribute(gemm_hmma_kernel,
                       cudaFuncAttributeMaxDynamicSharedMemorySize, SMEM_TOTAL);
  cudaFuncSetAttribute(reconstruct_hmma_kernel,
                       cudaFuncAttributeMaxDynamicSharedMemorySize, RS_TOTAL);

  // 0) x -> fp16
  convert_x_kernel<<<(TOKENS * IN_F) / (256 * 4), 256>>>(x);

  // 1) HMMA reconstruct w -> fp16 (128 o x 128 i per CTA)
  dim3 rgrid(IN_F / 128, OUT_F / 128);  // (32, 86)
  reconstruct_hmma_kernel<<<rgrid, 256, RS_TOTAL>>>(qweight, u, vt);

  // 2) HMMA GEMM (BK=128, GS=2, 8 warps, 64x64 warp tile, ping-pong)
  dim3 ggrid(OUT_F / BN, TOKENS / BM);  // (43, 16)
  gemm_hmma_kernel<<<ggrid, NTHR, SMEM_TOTAL>>>(y);
}

// round 16
// speedup vs baseline: 1.0569x; 1.0569x over previous
#include <cuda_runtime.h>
#include <cuda_fp16.h>
#include <cstdint>

#define W_BIT 4
#define OUT_F 11008
#define IN_F 4096
#define KRANK 16
#define TOKENS 2048
#define NBYTES (OUT_F * IN_F / 8)

// fp16 staging buffers (static device globals: allocation-free rule)
__device__ __align__(16) __half g_w[(size_t)OUT_F * (size_t)IN_F];
__device__ __align__(16) __half g_x[(size_t)TOKENS * (size_t)IN_F];

// ---------------------------------------------------------------------------
// PTX helpers (baseline compute_103-safe: cp.async / ldmatrix / mma.sync only)
// ---------------------------------------------------------------------------
__device__ __forceinline__ uint32_t smem_u32(const void* p) {
  uint32_t a;
  asm("{ .reg .u64 t; cvta.to.shared.u64 t, %1; cvt.u32.u64 %0, t; }"
      : "=r"(a) : "l"(p));
  return a;
}

#define CP_ASYNC16(dst, src) \
  asm volatile("cp.async.cg.shared.global [%0], [%1], 16;" ::"r"(dst), "l"(src) : "memory")
#define CP_COMMIT() asm volatile("cp.async.commit_group;" ::: "memory")
#define CP_WAIT(n)  asm volatile("cp.async.wait_group %0;" ::"n"(n) : "memory")

#define LDSM_X4(r, addr)                                                  \
  asm volatile(                                                           \
      "ldmatrix.sync.aligned.m8n8.x4.shared.b16 {%0,%1,%2,%3}, [%4];"     \
      : "=r"((r)[0]), "=r"((r)[1]), "=r"((r)[2]), "=r"((r)[3])            \
      : "r"(addr))

#define LDSM_X4_T(r, addr)                                                \
  asm volatile(                                                           \
      "ldmatrix.sync.aligned.m8n8.x4.trans.shared.b16 {%0,%1,%2,%3}, [%4];" \
      : "=r"((r)[0]), "=r"((r)[1]), "=r"((r)[2]), "=r"((r)[3])            \
      : "r"(addr))

#define MMA16816(d, a, b)                                                 \
  asm volatile(                                                           \
      "mma.sync.aligned.m16n8k16.row.col.f32.f16.f16.f32 "                \
      "{%0,%1,%2,%3}, {%4,%5,%6,%7}, {%8,%9}, {%0,%1,%2,%3};"             \
      : "+f"((d)[0]), "+f"((d)[1]), "+f"((d)[2]), "+f"((d)[3])            \
      : "r"((a)[0]), "r"((a)[1]), "r"((a)[2]), "r"((a)[3]),               \
        "r"((b)[0]), "r"((b)[1]))

__device__ __forceinline__ float xor_sign(float p, unsigned s) {
  return __uint_as_float(__float_as_uint(p) ^ s);
}

// ---------------------------------------------------------------------------
// Kernel 0: x -> fp16
// ---------------------------------------------------------------------------
__global__ __launch_bounds__(256) void convert_x_kernel(const float* __restrict__ x) {
  size_t i = ((size_t)blockIdx.x * 256 + threadIdx.x) * 4;
  float4 v = *(const float4*)(x + i);
  __half2 h0 = __floats2half2_rn(v.x, v.y);
  __half2 h1 = __floats2half2_rn(v.z, v.w);
  uint2 p;
  p.x = *(const unsigned*)&h0;
  p.y = *(const unsigned*)&h1;
  *(uint2*)(g_x + i) = p;
}

// ---------------------------------------------------------------------------
// Kernel 1: HMMA reconstruct (R10 version — validated, unchanged).
// ---------------------------------------------------------------------------
#define US_OFF 0
#define US_BSTR (128 * 48)
#define VT_OFF 24576
#define VT_BSTR (16 * 272)
#define QS_OFF (24576 + 17408)
#define RS_TOTAL (QS_OFF + 4 * 128 * 16)  // 50176 B

__global__ __launch_bounds__(256, 1) void reconstruct_hmma_kernel(
    const int* __restrict__ qweight, const float* __restrict__ u,
    const float* __restrict__ vt) {
  extern __shared__ char rs[];
  const uint32_t sb = smem_u32(rs);
  const int tid = threadIdx.x;
  const int lane = tid & 31;
  const int wid = tid >> 5;
  const int wm = wid & 1;
  const int wn = wid >> 1;
  const int i_base = blockIdx.x * 128;
  const int o_base = blockIdx.y * 128;

#pragma unroll
  for (int j = 0; j < 8; j++) {
    const int s = tid + j * 256;
    const int b = s >> 9;
    const int rem = s & 511;

    {  // u
      const int o = rem >> 2, k4 = rem & 3;
      const float4 uf = *(const float4*)(
          u + ((size_t)b * OUT_F + o_base + o) * KRANK + k4 * 4);
      __half2 h0 = __floats2half2_rn(uf.x, uf.y);
      __half2 h1 = __floats2half2_rn(uf.z, uf.w);
      uint2 pk = make_uint2(*(const unsigned*)&h0, *(const unsigned*)&h1);
      *(uint2*)(rs + US_OFF + b * US_BSTR + o * 48 + k4 * 8) = pk;
    }
    {  // vt
      const int k = rem >> 5, c4 = (rem & 31) * 4;
      const float4 vf = *(const float4*)(
          vt + ((size_t)b * KRANK + k) * IN_F + i_base + c4);
      __half2 h0 = __floats2half2_rn(vf.x, vf.y);
      __half2 h1 = __floats2half2_rn(vf.z, vf.w);
      uint2 pk = make_uint2(*(const unsigned*)&h0, *(const unsigned*)&h1);
      *(uint2*)(rs + VT_OFF + b * VT_BSTR + k * 272 + c4 * 2) = pk;
    }
    {  // qweight (with i-tile offset)
      const int o = rem >> 2, q4 = rem & 3;
      const int4 qi = *(const int4*)(
          qweight + (size_t)b * NBYTES + (size_t)(o_base + o) * (IN_F / 8) +
          (i_base >> 3) + q4 * 4);
      const unsigned pk = (unsigned)qi.x | ((unsigned)qi.y << 8) |
                          ((unsigned)qi.z << 16) | ((unsigned)qi.w << 24);
      *(unsigned*)(rs + QS_OFF + b * 2048 + o * 16 + q4 * 4) = pk;
    }
  }
  __syncthreads();

  float acc[4][4][4];
#pragma unroll
  for (int mt = 0; mt < 4; mt++)
#pragma unroll
    for (int nt = 0; nt < 4; nt++)
#pragma unroll
      for (int q = 0; q < 4; q++) acc[mt][nt][q] = 0.0f;

  const int j0 = (lane & 3) * 2;
  const char* qsm = rs + QS_OFF;

#pragma unroll
  for (int b = 0; b < W_BIT; b++) {
    uint32_t af[4][4];
#pragma unroll
    for (int mt = 0; mt < 4; mt++) {
      const uint32_t addr = sb + US_OFF + b * US_BSTR +
                            (wm * 64 + mt * 16 + (lane & 15)) * 48 +
                            (lane >> 4) * 16;
      LDSM_X4(af[mt], addr);
    }
    uint32_t bf[4][2];
#pragma unroll
    for (int p = 0; p < 2; p++) {
      const int k_r = ((lane >> 3) & 1) * 8 + (lane & 7);
      const int n_off = wn * 32 + p * 16 + (lane >> 4) * 8;
      const uint32_t addr = sb + VT_OFF + b * VT_BSTR + k_r * 272 + n_off * 2;
      uint32_t r[4];
      LDSM_X4_T(r, addr);
      bf[p * 2][0] = r[0]; bf[p * 2][1] = r[1];
      bf[p * 2 + 1][0] = r[2]; bf[p * 2 + 1][1] = r[3];
    }

#pragma unroll
    for (int mt = 0; mt < 4; mt++) {
      float p4[4][4];
#pragma unroll
      for (int nt = 0; nt < 4; nt++) {
        p4[nt][0] = 0.0f; p4[nt][1] = 0.0f;
        p4[nt][2] = 0.0f; p4[nt][3] = 0.0f;
        MMA16816(p4[nt], af[mt], bf[nt]);
      }
      const int o_lo = wm * 64 + mt * 16 + (lane >> 2);
      const int o_hi = o_lo + 8;
      const unsigned nb_lo =
          ~*(const unsigned*)(qsm + b * 2048 + o_lo * 16 + wn * 4);
      const unsigned nb_hi =
          ~*(const unsigned*)(qsm + b * 2048 + o_hi * 16 + wn * 4);
#pragma unroll
      for (int nt = 0; nt < 4; nt++) {
        const int sh = nt * 8 + j0;
        acc[mt][nt][0] += xor_sign(p4[nt][0], ((nb_lo >> sh) << 31));
        acc[mt][nt][1] += xor_sign(p4[nt][1], ((nb_lo >> (sh + 1)) << 31));
        acc[mt][nt][2] += xor_sign(p4[nt][2], ((nb_hi >> sh) << 31));
        acc[mt][nt][3] += xor_sign(p4[nt][3], ((nb_hi >> (sh + 1)) << 31));
      }
    }
  }

#pragma unroll
  for (int mt = 0; mt < 4; mt++) {
    const int o_lo = o_base + wm * 64 + mt * 16 + (lane >> 2);
#pragma unroll
    for (int nt = 0; nt < 4; nt++) {
      const int i0 = i_base + wn * 32 + nt * 8 + j0;
      __half2 hlo = __floats2half2_rn(acc[mt][nt][0], acc[mt][nt][1]);
      __half2 hhi = __floats2half2_rn(acc[mt][nt][2], acc[mt][nt][3]);
      *(unsigned*)(g_w + (size_t)o_lo * IN_F + i0) = *(const unsigned*)&hlo;
      *(unsigned*)(g_w + (size_t)(o_lo + 8) * IN_F + i0) = *(const unsigned*)&hhi;
    }
  }
}

// ---------------------------------------------------------------------------
// Kernel 2: HMMA fp16 GEMM, f32 accum (R14 config — best measured).
// CTA 128x256, BK=128, GS=2, 16 warps (4x4), warp tile 32x64,
// A+B register ping-pong. SINGLE barrier per iteration (top barrier of
// iter it orders consumption of stage (it+1)%2 in iter it-1 before its
// refill in iter it — bottom barrier was redundant).
// ---------------------------------------------------------------------------
#define BM 128
#define BN 256
#define BKK 128
#define GS 2
#define ROWB 272                          // 256B data + 16B pad per row
#define A_ST (BM * ROWB)                  // 34816 B
#define B_ST (BN * ROWB)                  // 69632 B
#define SMEM_TOTAL (GS * (A_ST + B_ST))   // 208896 B
#define NIT (IN_F / BKK)                  // 32
#define NTHR 512

__global__ __launch_bounds__(NTHR, 1) void gemm_hmma_kernel(float* __restrict__ Y) {
  extern __shared__ char smem[];
  const uint32_t sb = smem_u32(smem);
  const int tid = threadIdx.x;
  const int wid = tid >> 5;
  const int lane = tid & 31;
  const int m0 = blockIdx.y * BM;
  const int n0 = blockIdx.x * BN;
  const int wm = wid & 3;
  const int wn = wid >> 2;

  const __half* Ag = g_x + (size_t)m0 * IN_F;
  const __half* Bg = g_w + (size_t)n0 * IN_F;

  // fill: A = 2048 slots of 16B (4/thread), B = 4096 slots (8/thread)
  auto fill = [&](int s, int c) {
    const uint32_t ab = sb + s * A_ST;
    const uint32_t bb = sb + GS * A_ST + s * B_ST;
    const int k0 = c * BKK;
#pragma unroll
    for (int j = 0; j < 4; j++) {
      const int slot = tid + j * NTHR;
      const int row = slot >> 4, ch = slot & 15;
      CP_ASYNC16(ab + row * ROWB + ch * 16,
                 Ag + (size_t)row * IN_F + k0 + ch * 8);
    }
#pragma unroll
    for (int j = 0; j < 8; j++) {
      const int slot = tid + j * NTHR;
      const int row = slot >> 4, ch = slot & 15;
      CP_ASYNC16(bb + row * ROWB + ch * 16,
                 Bg + (size_t)row * IN_F + k0 + ch * 8);
    }
    CP_COMMIT();
  };

  float acc[2][8][4];
#pragma unroll
  for (int mt = 0; mt < 2; mt++)
#pragma unroll
    for (int nt = 0; nt < 8; nt++)
#pragma unroll
      for (int q = 0; q < 4; q++) acc[mt][nt][q] = 0.0f;

  fill(0, 0);  // prologue

  const int a_row_l = lane & 15;
  const int a_ch_l = (lane >> 4) * 16;
  const int b_g = lane >> 3;
  const int b_row_l = ((b_g >> 1) * 8) + (lane & 7);
  const int b_ch_l = (b_g & 1) * 16;

  const uint32_t a_lane_off = (wm * 32 + a_row_l) * ROWB + a_ch_l;
  const uint32_t b_lane_off = (wn * 64 + b_row_l) * ROWB + b_ch_l;

  for (int it = 0; it < NIT; it++) {
    CP_WAIT(0);
    __syncthreads();  // publishes stage it%GS; also orders last iter's
                      // consumption of stage (it+1)%GS before its refill

    const int c = it + 1;
    if (c < NIT) fill(c % GS, c);

    const int s = it % GS;
    const uint32_t ab = sb + s * A_ST + a_lane_off;
    const uint32_t bb = sb + GS * A_ST + s * B_ST + b_lane_off;

    uint32_t a[2][2][4];   // [buf][mt][frag]
    uint32_t b[2][8][2];   // [buf][nt][frag]

    auto load_a = [&](int buf, int kt) {
#pragma unroll
      for (int mt = 0; mt < 2; mt++)
        LDSM_X4(a[buf][mt], ab + mt * 16 * ROWB + kt * 32);
    };
    auto load_b = [&](int buf, int kt) {
#pragma unroll
      for (int np = 0; np < 4; np++) {
        uint32_t r[4];
        LDSM_X4(r, bb + np * 16 * ROWB + kt * 32);
        b[buf][np * 2][0] = r[0]; b[buf][np * 2][1] = r[1];
        b[buf][np * 2 + 1][0] = r[2]; b[buf][np * 2 + 1][1] = r[3];
      }
    };

    load_b(0, 0);
    load_a(0, 0);

#pragma unroll
    for (int kt = 0; kt < BKK / 16; kt++) {
      const int cur = kt & 1;
      if (kt < BKK / 16 - 1) {
        load_b(cur ^ 1, kt + 1);   // next-kt LDSMs before this kt's MMAs
        load_a(cur ^ 1, kt + 1);
      }
#pragma unroll
      for (int mt = 0; mt < 2; mt++)
#pragma unroll
        for (int nt = 0; nt < 8; nt++)
          MMA16816(acc[mt][nt], a[cur][mt], b[cur][nt]);
    }
    // no bottom barrier (redundant; see header comment)
  }

#pragma unroll
  for (int mt = 0; mt < 2; mt++) {
#pragma unroll
    for (int nt = 0; nt < 8; nt++) {
      const int r = m0 + wm * 32 + mt * 16 + (lane >> 2);
      const int cc = n0 + wn * 64 + nt * 8 + (lane & 3) * 2;
      float2 v0 = make_float2(acc[mt][nt][0], acc[mt][nt][1]);
      float2 v1 = make_float2(acc[mt][nt][2], acc[mt][nt][3]);
      *(float2*)(Y + (size_t)r * OUT_F + cc) = v0;
      *(float2*)(Y + (size_t)(r + 8) * OUT_F + cc) = v1;
    }
  }
}

// ---------------------------------------------------------------------------
// Launch: convert_x (legacy) runs CONCURRENT with reconstruct (s2) — they
// are independent (g_x vs g_w). Join before the GEMM. Event fork/join is
// graph-capture-legal; stream/event creation is host-side, no device alloc.
// ---------------------------------------------------------------------------
extern "C" void kernel_launch(void* const* d_in, const int* in_sizes, int n_in,
                              void* d_out, int out_size) {
  const float* x = (const float*)d_in[0];
  const int* qweight = (const int*)d_in[1];
  const float* u = (const float*)d_in[2];
  const float* vt = (const float*)d_in[3];
  float* y = (float*)d_out;
  (void)in_sizes; (void)n_in; (void)out_size;

  cudaFuncSetAttribute(gemm_hmma_kernel,
                       cudaFuncAttributeMaxDynamicSharedMemorySize, SMEM_TOTAL);
  cudaFuncSetAttribute(reconstruct_hmma_kernel,
                       cudaFuncAttributeMaxDynamicSharedMemorySize, RS_TOTAL);

  cudaStream_t s2;
  cudaStreamCreateWithFlags(&s2, cudaStreamNonBlocking);
  cudaEvent_t e0, e2;
  cudaEventCreateWithFlags(&e0, cudaEventDisableTiming);
  cudaEventCreateWithFlags(&e2, cudaEventDisableTiming);

  // fork point
  cudaEventRecord(e0, 0);
  cudaStreamWaitEvent(s2, e0, 0);

  // recon on s2 (82 us) hides convert on legacy (10 us)
  dim3 rgrid(IN_F / 128, OUT_F / 128);  // (32, 86)
  reconstruct_hmma_kernel<<<rgrid, 256, RS_TOTAL, s2>>>(qweight, u, vt);
  cudaEventRecord(e2, s2);

  convert_x_kernel<<<(TOKENS * IN_F) / (256 * 4), 256>>>(x);

  // join, then GEMM
  cudaStreamWaitEvent(0, e2, 0);
  dim3 ggrid(OUT_F / BN, TOKENS / BM);  // (43, 16)
  gemm_hmma_kernel<<<ggrid, NTHR, SMEM_TOTAL>>>(y);
}

// round 17
// speedup vs baseline: 1.0830x; 1.0247x over previous
#include <cuda_runtime.h>
#include <cuda_fp16.h>
#include <cstdint>

#define W_BIT 4
#define OUT_F 11008
#define IN_F 4096
#define KRANK 16
#define TOKENS 2048
#define NBYTES (OUT_F * IN_F / 8)

// fp16 staging buffers (static device globals: allocation-free rule)
__device__ __align__(16) __half g_w[(size_t)OUT_F * (size_t)IN_F];
__device__ __align__(16) __half g_x[(size_t)TOKENS * (size_t)IN_F];

// ---------------------------------------------------------------------------
// PTX helpers (baseline compute_103-safe: cp.async / ldmatrix / mma.sync only)
// ---------------------------------------------------------------------------
__device__ __forceinline__ uint32_t smem_u32(const void* p) {
  uint32_t a;
  asm("{ .reg .u64 t; cvta.to.shared.u64 t, %1; cvt.u32.u64 %0, t; }"
      : "=r"(a) : "l"(p));
  return a;
}

#define CP_ASYNC16(dst, src) \
  asm volatile("cp.async.cg.shared.global [%0], [%1], 16;" ::"r"(dst), "l"(src) : "memory")
#define CP_COMMIT() asm volatile("cp.async.commit_group;" ::: "memory")
#define CP_WAIT(n)  asm volatile("cp.async.wait_group %0;" ::"n"(n) : "memory")

#define LDSM_X4(r, addr)                                                  \
  asm volatile(                                                           \
      "ldmatrix.sync.aligned.m8n8.x4.shared.b16 {%0,%1,%2,%3}, [%4];"     \
      : "=r"((r)[0]), "=r"((r)[1]), "=r"((r)[2]), "=r"((r)[3])            \
      : "r"(addr))

#define LDSM_X4_T(r, addr)                                                \
  asm volatile(                                                           \
      "ldmatrix.sync.aligned.m8n8.x4.trans.shared.b16 {%0,%1,%2,%3}, [%4];" \
      : "=r"((r)[0]), "=r"((r)[1]), "=r"((r)[2]), "=r"((r)[3])            \
      : "r"(addr))

#define MMA16816(d, a, b)                                                 \
  asm volatile(                                                           \
      "mma.sync.aligned.m16n8k16.row.col.f32.f16.f16.f32 "                \
      "{%0,%1,%2,%3}, {%4,%5,%6,%7}, {%8,%9}, {%0,%1,%2,%3};"             \
      : "+f"((d)[0]), "+f"((d)[1]), "+f"((d)[2]), "+f"((d)[3])            \
      : "r"((a)[0]), "r"((a)[1]), "r"((a)[2]), "r"((a)[3]),               \
        "r"((b)[0]), "r"((b)[1]))

__device__ __forceinline__ float xor_sign(float p, unsigned s) {
  return __uint_as_float(__float_as_uint(p) ^ s);
}

// ---------------------------------------------------------------------------
// Kernel 0: x -> fp16
// ---------------------------------------------------------------------------
__global__ __launch_bounds__(256) void convert_x_kernel(const float* __restrict__ x) {
  size_t i = ((size_t)blockIdx.x * 256 + threadIdx.x) * 4;
  float4 v = *(const float4*)(x + i);
  __half2 h0 = __floats2half2_rn(v.x, v.y);
  __half2 h1 = __floats2half2_rn(v.z, v.w);
  uint2 p;
  p.x = *(const unsigned*)&h0;
  p.y = *(const unsigned*)&h1;
  *(uint2*)(g_x + i) = p;
}

// ---------------------------------------------------------------------------
// Kernel 1: HMMA reconstruct. CTA tile: 64 o x 128 i (halved o-tile for
// 2 CTAs/SM occupancy; R16 profile showed 252 regs -> 1 CTA/SM -> latency
// bound at 11.8% occ). 8 warps (2x4), warp tile 32 o x 32 i, acc 32 regs.
// __launch_bounds__(256,2) caps regs at 128 -> 2 CTAs/SM.
// ---------------------------------------------------------------------------
#define US_OFF 0
#define US_BSTR (64 * 48)                 // 3072 per bit
#define VT_OFF (4 * US_BSTR)              // 12288
#define VT_BSTR (16 * 272)                // 4352 per bit
#define QS_OFF (VT_OFF + 4 * VT_BSTR)     // 29696
#define RS_TOTAL (QS_OFF + 4 * 64 * 16)   // 33792 B

__global__ __launch_bounds__(256, 2) void reconstruct_hmma_kernel(
    const int* __restrict__ qweight, const float* __restrict__ u,
    const float* __restrict__ vt) {
  extern __shared__ char rs[];
  const uint32_t sb = smem_u32(rs);
  const int tid = threadIdx.x;
  const int lane = tid & 31;
  const int wid = tid >> 5;
  const int wm = wid & 1;   // 2 warp rows (o), 32 each
  const int wn = wid >> 1;  // 4 warp cols (i), 32 each
  const int i_base = blockIdx.x * 128;
  const int o_base = blockIdx.y * 64;

  // vt staging: 2048 float4 slots (8/thread) — unchanged size (i x k only)
#pragma unroll
  for (int j = 0; j < 8; j++) {
    const int s = tid + j * 256;
    const int b = s >> 9;
    const int rem = s & 511;
    const int k = rem >> 5, c4 = (rem & 31) * 4;
    const float4 vf = *(const float4*)(
        vt + ((size_t)b * KRANK + k) * IN_F + i_base + c4);
    __half2 h0 = __floats2half2_rn(vf.x, vf.y);
    __half2 h1 = __floats2half2_rn(vf.z, vf.w);
    uint2 pk = make_uint2(*(const unsigned*)&h0, *(const unsigned*)&h1);
    *(uint2*)(rs + VT_OFF + b * VT_BSTR + k * 272 + c4 * 2) = pk;
  }
  // u staging: 1024 slots (4/thread)
#pragma unroll
  for (int j = 0; j < 4; j++) {
    const int s = tid + j * 256;
    const int b = s >> 8;
    const int rem = s & 255;
    const int o = rem >> 2, k4 = rem & 3;
    const float4 uf = *(const float4*)(
        u + ((size_t)b * OUT_F + o_base + o) * KRANK + k4 * 4);
    __half2 h0 = __floats2half2_rn(uf.x, uf.y);
    __half2 h1 = __floats2half2_rn(uf.z, uf.w);
    uint2 pk = make_uint2(*(const unsigned*)&h0, *(const unsigned*)&h1);
    *(uint2*)(rs + US_OFF + b * US_BSTR + o * 48 + k4 * 8) = pk;
  }
  // qweight staging: 1024 u32 slots (4/thread)
#pragma unroll
  for (int j = 0; j < 4; j++) {
    const int s = tid + j * 256;
    const int b = s >> 8;
    const int rem = s & 255;
    const int o = rem >> 2, q4 = rem & 3;
    const int4 qi = *(const int4*)(
        qweight + (size_t)b * NBYTES + (size_t)(o_base + o) * (IN_F / 8) +
        (i_base >> 3) + q4 * 4);
    const unsigned pk = (unsigned)qi.x | ((unsigned)qi.y << 8) |
                        ((unsigned)qi.z << 16) | ((unsigned)qi.w << 24);
    *(unsigned*)(rs + QS_OFF + b * 1024 + o * 16 + q4 * 4) = pk;
  }
  __syncthreads();

  float acc[2][4][4];
#pragma unroll
  for (int mt = 0; mt < 2; mt++)
#pragma unroll
    for (int nt = 0; nt < 4; nt++)
#pragma unroll
      for (int q = 0; q < 4; q++) acc[mt][nt][q] = 0.0f;

  const int j0 = (lane & 3) * 2;
  const char* qsm = rs + QS_OFF;

#pragma unroll
  for (int b = 0; b < W_BIT; b++) {
    uint32_t af[2][4];
#pragma unroll
    for (int mt = 0; mt < 2; mt++) {
      const uint32_t addr = sb + US_OFF + b * US_BSTR +
                            (wm * 32 + mt * 16 + (lane & 15)) * 48 +
                            (lane >> 4) * 16;
      LDSM_X4(af[mt], addr);
    }
    uint32_t bf[4][2];
#pragma unroll
    for (int p = 0; p < 2; p++) {
      const int k_r = ((lane >> 3) & 1) * 8 + (lane & 7);
      const int n_off = wn * 32 + p * 16 + (lane >> 4) * 8;
      const uint32_t addr = sb + VT_OFF + b * VT_BSTR + k_r * 272 + n_off * 2;
      uint32_t r[4];
      LDSM_X4_T(r, addr);
      bf[p * 2][0] = r[0]; bf[p * 2][1] = r[1];
      bf[p * 2 + 1][0] = r[2]; bf[p * 2 + 1][1] = r[3];
    }

#pragma unroll
    for (int mt = 0; mt < 2; mt++) {
      float p4[4][4];
#pragma unroll
      for (int nt = 0; nt < 4; nt++) {
        p4[nt][0] = 0.0f; p4[nt][1] = 0.0f;
        p4[nt][2] = 0.0f; p4[nt][3] = 0.0f;
        MMA16816(p4[nt], af[mt], bf[nt]);
      }
      const int o_lo = wm * 32 + mt * 16 + (lane >> 2);
      const int o_hi = o_lo + 8;
      const unsigned nb_lo =
          ~*(const unsigned*)(qsm + b * 1024 + o_lo * 16 + wn * 4);
      const unsigned nb_hi =
          ~*(const unsigned*)(qsm + b * 1024 + o_hi * 16 + wn * 4);
#pragma unroll
      for (int nt = 0; nt < 4; nt++) {
        const int sh = nt * 8 + j0;
        acc[mt][nt][0] += xor_sign(p4[nt][0], ((nb_lo >> sh) << 31));
        acc[mt][nt][1] += xor_sign(p4[nt][1], ((nb_lo >> (sh + 1)) << 31));
        acc[mt][nt][2] += xor_sign(p4[nt][2], ((nb_hi >> sh) << 31));
        acc[mt][nt][3] += xor_sign(p4[nt][3], ((nb_hi >> (sh + 1)) << 31));
      }
    }
  }

#pragma unroll
  for (int mt = 0; mt < 2; mt++) {
    const int o_lo = o_base + wm * 32 + mt * 16 + (lane >> 2);
#pragma unroll
    for (int nt = 0; nt < 4; nt++) {
      const int i0 = i_base + wn * 32 + nt * 8 + j0;
      __half2 hlo = __floats2half2_rn(acc[mt][nt][0], acc[mt][nt][1]);
      __half2 hhi = __floats2half2_rn(acc[mt][nt][2], acc[mt][nt][3]);
      *(unsigned*)(g_w + (size_t)o_lo * IN_F + i0) = *(const unsigned*)&hlo;
      *(unsigned*)(g_w + (size_t)(o_lo + 8) * IN_F + i0) = *(const unsigned*)&hhi;
    }
  }
}

// ---------------------------------------------------------------------------
// Kernel 2: HMMA fp16 GEMM, f32 accum (R16 version — best measured).
// CTA 128x256, BK=128, GS=2, 16 warps (4x4), warp tile 32x64,
// A+B register ping-pong, single barrier per iteration.
// ---------------------------------------------------------------------------
#define BM 128
#define BN 256
#define BKK 128
#define GS 2
#define ROWB 272                          // 256B data + 16B pad per row
#define A_ST (BM * ROWB)                  // 34816 B
#define B_ST (BN * ROWB)                  // 69632 B
#define SMEM_TOTAL (GS * (A_ST + B_ST))   // 208896 B
#define NIT (IN_F / BKK)                  // 32
#define NTHR 512

__global__ __launch_bounds__(NTHR, 1) void gemm_hmma_kernel(float* __restrict__ Y) {
  extern __shared__ char smem[];
  const uint32_t sb = smem_u32(smem);
  const int tid = threadIdx.x;
  const int wid = tid >> 5;
  const int lane = tid & 31;
  const int m0 = blockIdx.y * BM;
  const int n0 = blockIdx.x * BN;
  const int wm = wid & 3;
  const int wn = wid >> 2;

  const __half* Ag = g_x + (size_t)m0 * IN_F;
  const __half* Bg = g_w + (size_t)n0 * IN_F;

  auto fill = [&](int s, int c) {
    const uint32_t ab = sb + s * A_ST;
    const uint32_t bb = sb + GS * A_ST + s * B_ST;
    const int k0 = c * BKK;
#pragma unroll
    for (int j = 0; j < 4; j++) {
      const int slot = tid + j * NTHR;
      const int row = slot >> 4, ch = slot & 15;
      CP_ASYNC16(ab + row * ROWB + ch * 16,
                 Ag + (size_t)row * IN_F + k0 + ch * 8);
    }
#pragma unroll
    for (int j = 0; j < 8; j++) {
      const int slot = tid + j * NTHR;
      const int row = slot >> 4, ch = slot & 15;
      CP_ASYNC16(bb + row * ROWB + ch * 16,
                 Bg + (size_t)row * IN_F + k0 + ch * 8);
    }
    CP_COMMIT();
  };

  float acc[2][8][4];
#pragma unroll
  for (int mt = 0; mt < 2; mt++)
#pragma unroll
    for (int nt = 0; nt < 8; nt++)
#pragma unroll
      for (int q = 0; q < 4; q++) acc[mt][nt][q] = 0.0f;

  fill(0, 0);  // prologue

  const int a_row_l = lane & 15;
  const int a_ch_l = (lane >> 4) * 16;
  const int b_g = lane >> 3;
  const int b_row_l = ((b_g >> 1) * 8) + (lane & 7);
  const int b_ch_l = (b_g & 1) * 16;

  const uint32_t a_lane_off = (wm * 32 + a_row_l) * ROWB + a_ch_l;
  const uint32_t b_lane_off = (wn * 64 + b_row_l) * ROWB + b_ch_l;

  for (int it = 0; it < NIT; it++) {
    CP_WAIT(0);
    __syncthreads();  // publishes stage it%GS; also orders last iter's
                      // consumption of stage (it+1)%GS before its refill

    const int c = it + 1;
    if (c < NIT) fill(c % GS, c);

    const int s = it % GS;
    const uint32_t ab = sb + s * A_ST + a_lane_off;
    const uint32_t bb = sb + GS * A_ST + s * B_ST + b_lane_off;

    uint32_t a[2][2][4];   // [buf][mt][frag]
    uint32_t b[2][8][2];   // [buf][nt][frag]

    auto load_a = [&](int buf, int kt) {
#pragma unroll
      for (int mt = 0; mt < 2; mt++)
        LDSM_X4(a[buf][mt], ab + mt * 16 * ROWB + kt * 32);
    };
    auto load_b = [&](int buf, int kt) {
#pragma unroll
      for (int np = 0; np < 4; np++) {
        uint32_t r[4];
        LDSM_X4(r, bb + np * 16 * ROWB + kt * 32);
        b[buf][np * 2][0] = r[0]; b[buf][np * 2][1] = r[1];
        b[buf][np * 2 + 1][0] = r[2]; b[buf][np * 2 + 1][1] = r[3];
      }
    };

    load_b(0, 0);
    load_a(0, 0);

#pragma unroll
    for (int kt = 0; kt < BKK / 16; kt++) {
      const int cur = kt & 1;
      if (kt < BKK / 16 - 1) {
        load_b(cur ^ 1, kt + 1);   // next-kt LDSMs before this kt's MMAs
        load_a(cur ^ 1, kt + 1);
      }
#pragma unroll
      for (int mt = 0; mt < 2; mt++)
#pragma unroll
        for (int nt = 0; nt < 8; nt++)
          MMA16816(acc[mt][nt], a[cur][mt], b[cur][nt]);
    }
  }

#pragma unroll
  for (int mt = 0; mt < 2; mt++) {
#pragma unroll
    for (int nt = 0; nt < 8; nt++) {
      const int r = m0 + wm * 32 + mt * 16 + (lane >> 2);
      const int cc = n0 + wn * 64 + nt * 8 + (lane & 3) * 2;
      float2 v0 = make_float2(acc[mt][nt][0], acc[mt][nt][1]);
      float2 v1 = make_float2(acc[mt][nt][2], acc[mt][nt][3]);
      *(float2*)(Y + (size_t)r * OUT_F + cc) = v0;
      *(float2*)(Y + (size_t)(r + 8) * OUT_F + cc) = v1;
    }
  }
}

// ---------------------------------------------------------------------------
// Launch: convert_x (legacy) || reconstruct (s2), join, GEMM (R16 proven).
// ---------------------------------------------------------------------------
extern "C" void kernel_launch(void* const* d_in, const int* in_sizes, int n_in,
                              void* d_out, int out_size) {
  const float* x = (const float*)d_in[0];
  const int* qweight = (const int*)d_in[1];
  const float* u = (const float*)d_in[2];
  const float* vt = (const float*)d_in[3];
  float* y = (float*)d_out;
  (void)in_sizes; (void)n_in; (void)out_size;

  cudaFuncSetAttribute(gemm_hmma_kernel,
                       cudaFuncAttributeMaxDynamicSharedMemorySize, SMEM_TOTAL);
  cudaFuncSetAttribute(reconstruct_hmma_kernel,
                       cudaFuncAttributeMaxDynamicSharedMemorySize, RS_TOTAL);

  cudaStream_t s2;
  cudaStreamCreateWithFlags(&s2, cudaStreamNonBlocking);
  cudaEvent_t e0, e2;
  cudaEventCreateWithFlags(&e0, cudaEventDisableTiming);
  cudaEventCreateWithFlags(&e2, cudaEventDisableTiming);

  // fork point
  cudaEventRecord(e0, 0);
  cudaStreamWaitEvent(s2, e0, 0);

  // recon on s2 hides convert on legacy
  dim3 rgrid(IN_F / 128, OUT_F / 64);  // (32, 172)
  reconstruct_hmma_kernel<<<rgrid, 256, RS_TOTAL, s2>>>(qweight, u, vt);
  cudaEventRecord(e2, s2);

  convert_x_kernel<<<(TOKENS * IN_F) / (256 * 4), 256>>>(x);

  // join, then GEMM
  cudaStreamWaitEvent(0, e2, 0);
  dim3 ggrid(OUT_F / BN, TOKENS / BM);  // (43, 16)
  gemm_hmma_kernel<<<ggrid, NTHR, SMEM_TOTAL>>>(y);
}